// round 11
// baseline (speedup 1.0000x reference)
#include <cuda_runtime.h>
#include <cuda_fp16.h>
#include <cstdint>
#include <math.h>

#define BS    2
#define SEQ   2048
#define DEMB  1024
#define DATTN 1024
#define NH    16
#define HD    64
#define MROWS (BS*SEQ)   // 4096

#define LOG2E 1.4426950408889634f
#define QSCALE (0.125f * LOG2E)   // folded softmax scale (log2 domain)

// ---------------------------------------------------------------------------
// Scratch (device globals -- no allocation allowed)
// ---------------------------------------------------------------------------
__device__ __half g_xh[MROWS * DEMB];
__device__ __half g_wqh[DATTN * DEMB];
__device__ __half g_wkh[DATTN * DEMB];
__device__ __half g_wvh[DATTN * DEMB];
__device__ __half g_woh[DATTN * DATTN];
__device__ __half g_qh[MROWS * DATTN];
__device__ __half g_kh[MROWS * DATTN];
__device__ __half g_vh[MROWS * DATTN];
__device__ __half g_ch[MROWS * DATTN];

// ---------------------------------------------------------------------------
// PTX helpers
// ---------------------------------------------------------------------------
__device__ __forceinline__ uint32_t smem_u32(const void* p) {
    uint32_t a;
    asm("{ .reg .u64 t; cvta.to.shared.u64 t, %1; cvt.u32.u64 %0, t; }"
        : "=r"(a) : "l"(p));
    return a;
}

#define LDMATRIX_X4(r0, r1, r2, r3, addr) \
    asm volatile("ldmatrix.sync.aligned.m8n8.x4.shared.b16 {%0,%1,%2,%3}, [%4];" \
        : "=r"(r0), "=r"(r1), "=r"(r2), "=r"(r3) : "r"(addr))

#define LDMATRIX_X4T(r0, r1, r2, r3, addr) \
    asm volatile("ldmatrix.sync.aligned.m8n8.x4.trans.shared.b16 {%0,%1,%2,%3}, [%4];" \
        : "=r"(r0), "=r"(r1), "=r"(r2), "=r"(r3) : "r"(addr))

#define MMA_F16(d, a, b) \
    asm volatile("mma.sync.aligned.m16n8k16.row.col.f32.f16.f16.f32 " \
        "{%0,%1,%2,%3}, {%4,%5,%6,%7}, {%8,%9}, {%0,%1,%2,%3};" \
        : "+f"((d)[0]), "+f"((d)[1]), "+f"((d)[2]), "+f"((d)[3]) \
        : "r"((a)[0]), "r"((a)[1]), "r"((a)[2]), "r"((a)[3]), \
          "r"((b)[0]), "r"((b)[1]))

#define CP_ASYNC16(saddr, gptr) \
    asm volatile("cp.async.cg.shared.global [%0], [%1], 16;" \
        :: "r"(saddr), "l"(gptr))
#define CP_COMMIT() asm volatile("cp.async.commit_group;" ::: "memory")
#define CP_WAIT(n)  asm volatile("cp.async.wait_group %0;" :: "n"(n) : "memory")

__device__ __forceinline__ uint32_t sw128(uint32_t bo) {
    return bo ^ ((bo >> 3) & 0x70);
}

__device__ __forceinline__ uint32_t pack_h2(float x, float y) {
    __half2 h = __floats2half2_rn(x, y);
    return *reinterpret_cast<uint32_t*>(&h);
}

// ---------------------------------------------------------------------------
// Fused fp32 -> fp16 convert: x + 4 weights, one launch. (unchanged)
// ---------------------------------------------------------------------------
__global__ __launch_bounds__(256) void split_all(
    const float* __restrict__ x,  __half* __restrict__ xh,
    const float* __restrict__ wq, __half* __restrict__ qh,
    const float* __restrict__ wk, __half* __restrict__ kh,
    const float* __restrict__ wv, __half* __restrict__ vh,
    const float* __restrict__ wo, __half* __restrict__ oh)
{
    int blk = blockIdx.x;
    const float* src;
    __half* hi;
    int local;
    if (blk < 4096) { src = x; hi = xh; local = blk; }
    else {
        int w = (blk - 4096) >> 10;
        local = (blk - 4096) & 1023;
        src = (w == 0) ? wq : (w == 1) ? wk : (w == 2) ? wv : wo;
        hi  = (w == 0) ? qh : (w == 1) ? kh : (w == 2) ? vh : oh;
    }
    int i = local * 1024 + threadIdx.x * 4;
    float4 v = *(const float4*)(src + i);
    *(uint2*)(hi + i) = make_uint2(pack_h2(v.x, v.y), pack_h2(v.z, v.w));
}

// ---------------------------------------------------------------------------
// Persistent HMMA fp16 GEMM: C = Ah*Bh. CTA tile 128x128, BK=64, 3x32KB
// stages. NEW: 128 threads / 4 warps, warp tile 64x64 (2x2 warp grid).
// MMA:LDSM ratio 4.0, 32 independent MMAs per ks, ~180 regs (not RF-capped).
// 2 CTAs/SM (smem-bound). Tile id -> (z, m, n), n fastest.
// ---------------------------------------------------------------------------
#define GK 1024
#define NKT (GK / 64)     // 16
#define STG 32768u
#define NTM (MROWS / 128) // 32
#define NTN (DATTN / 128) // 8

__global__ __launch_bounds__(128, 2) void gemm_hmma(
    const __half* __restrict__ Ah,
    const __half* __restrict__ Bh0, const __half* __restrict__ Bh1,
    const __half* __restrict__ Bh2,
    const float* __restrict__ bias,
    float* __restrict__ Cf,
    __half* __restrict__ H0, __half* __restrict__ H1, __half* __restrict__ H2,
    int ntiles, int doScaleQ)
{
    extern __shared__ char smem[];
    const uint32_t sbase = smem_u32(smem);

    const int tid = threadIdx.x;
    const int wid = tid >> 5;        // 0..3
    const int lid = tid & 31;
    const int warp_m = wid >> 1;     // 0..1 (64 rows each)
    const int warp_n = wid & 1;      // 0..1 (64 cols each)

    const uint32_t a_row = warp_m * 64 + (lid & 15);
    const uint32_t a_cb  = (lid >> 4) * 16;
    const uint32_t b_mi  = lid >> 3;
    const uint32_t b_rl  = (b_mi >> 1) * 8 + (lid & 7);
    const uint32_t b_cb  = (b_mi & 1) * 16;
    const int gi = lid >> 2;
    const int ti = lid & 3;

    for (int tile = blockIdx.x; tile < ntiles; tile += gridDim.x) {
        const int z  = tile >> 8;
        const int rm = tile & 255;
        const int m0 = (rm >> 3) * 128;
        const int n0 = (rm & 7) * 128;

        const __half* Bh = (z == 0) ? Bh0 : (z == 1) ? Bh1 : Bh2;
        __half* Hs = (z == 0) ? H0 : (z == 1) ? H1 : H2;

        // stage = [A 16K][B 16K]; 2048 chunks / 128 thr = 16 per thread
        auto load_stage = [&](int kt, int s) {
            const uint32_t so = sbase + s * STG;
#pragma unroll
            for (int it = 0; it < 16; it++) {
                int idx = it * 128 + tid;      // 0..2047
                int t   = idx >> 10;           // 0=A 1=B
                int r   = (idx >> 3) & 127;
                int c   = idx & 7;
                uint32_t sw = sw128((uint32_t)(r * 128 + c * 16));
                size_t g = (size_t)((t ? n0 : m0) + r) * GK + kt * 64 + c * 8;
                CP_ASYNC16(so + t * 16384 + sw, (t ? Bh : Ah) + g);
            }
        };

        float acc[4][8][4];
#pragma unroll
        for (int i = 0; i < 4; i++)
#pragma unroll
            for (int j = 0; j < 8; j++)
#pragma unroll
                for (int r = 0; r < 4; r++) acc[i][j][r] = 0.0f;

        load_stage(0, 0); CP_COMMIT();
        load_stage(1, 1); CP_COMMIT();

        for (int kt = 0; kt < NKT; kt++) {
            if (kt + 1 < NKT) CP_WAIT(1); else CP_WAIT(0);
            __syncthreads();
            if (kt + 2 < NKT) {
                load_stage(kt + 2, (kt + 2) % 3);
                CP_COMMIT();
            }

            const uint32_t pAH = sbase + (kt % 3) * STG;
            const uint32_t pBH = pAH + 16384;

#pragma unroll
            for (int ks = 0; ks < 4; ks++) {
                // B: 64 cols = 4 ldmatrix.x4 -> 8 n8 fragments
                uint32_t bh[8][2];
#pragma unroll
                for (int j2 = 0; j2 < 4; j2++) {
                    uint32_t off = sw128((warp_n * 64 + j2 * 16 + b_rl) * 128
                                         + ks * 32 + b_cb);
                    uint32_t r0, r1, r2, r3;
                    LDMATRIX_X4(r0, r1, r2, r3, pBH + off);
                    bh[j2*2][0] = r0; bh[j2*2][1] = r1;
                    bh[j2*2+1][0] = r2; bh[j2*2+1][1] = r3;
                }
                // A: 64 rows = 4 ldmatrix.x4
#pragma unroll
                for (int i = 0; i < 4; i++) {
                    uint32_t ah[4];
                    uint32_t off = sw128((a_row + i * 16) * 128 + ks * 32 + a_cb);
                    LDMATRIX_X4(ah[0], ah[1], ah[2], ah[3], pAH + off);
#pragma unroll
                    for (int j = 0; j < 8; j++)
                        MMA_F16(acc[i][j], ah, bh[j]);
                }
            }
        }
        __syncthreads();   // stage smem -> epilogue staging

        const float sc = (doScaleQ && z == 0) ? QSCALE : 1.0f;
        float* Cs = (float*)smem;
#pragma unroll
        for (int i = 0; i < 4; i++)
#pragma unroll
            for (int j = 0; j < 8; j++) {
                int row = warp_m * 64 + i * 16 + gi;
                int col = warp_n * 64 + j * 8 + ti * 2;
                Cs[row * 132 + col]           = acc[i][j][0];
                Cs[row * 132 + col + 1]       = acc[i][j][1];
                Cs[(row + 8) * 132 + col]     = acc[i][j][2];
                Cs[(row + 8) * 132 + col + 1] = acc[i][j][3];
            }
        __syncthreads();

#pragma unroll
        for (int it = 0; it < 32; it++) {
            int idx = it * 128 + tid;   // 0..4095
            int r   = idx >> 5;
            int c4  = (idx & 31) * 4;
            float4 v = *(float4*)(Cs + r * 132 + c4);
            size_t go = (size_t)(m0 + r) * DATTN + n0 + c4;
            if (Hs) {
                *(uint2*)(Hs + go) =
                    make_uint2(pack_h2(v.x * sc, v.y * sc),
                               pack_h2(v.z * sc, v.w * sc));
            } else {
                if (bias) {
                    float4 bv = *(const float4*)(bias + n0 + c4);
                    v.x += bv.x; v.y += bv.y; v.z += bv.z; v.w += bv.w;
                }
                *(float4*)(Cf + go) = v;
            }
        }
        __syncthreads();
    }
}

// ---------------------------------------------------------------------------
// HMMA fp16 causal flash attention (unchanged from round 10).
// Br=128, Bc=64, D=64, 2 CTAs/SM. Q pre-scaled; no online max;
// qt-paired balanced grid (256 CTAs).
// ---------------------------------------------------------------------------
__global__ __launch_bounds__(256, 2) void attn_hmma(
    const __half* __restrict__ Qh,
    const __half* __restrict__ Kh,
    const __half* __restrict__ Vh,
    __half* __restrict__ Ch)
{
    extern __shared__ char smem[];
    const uint32_t sb = smem_u32(smem);
    const int tid = threadIdx.x, wid = tid >> 5, lid = tid & 31;
    const int gi = lid >> 2, ci = lid & 3;
    const int pi = blockIdx.x;
    const int h = blockIdx.y, b = blockIdx.z;

    const uint32_t ST = 16384, STSZ = 16384;

    const uint32_t a_row = wid * 16 + (lid & 15);
    const uint32_t a_cb  = (lid >> 4) * 16;
    const int b_mi = lid >> 3;
    const uint32_t b_rl = (uint32_t)((b_mi >> 1) * 8 + (lid & 7));
    const uint32_t b_cb = (uint32_t)((b_mi & 1) * 16);
    const uint32_t v_key = (uint32_t)(lid & 15);
    const uint32_t v_cb  = (uint32_t)((lid >> 4) * 16);

    const int NQT = SEQ / 128;

#pragma unroll 1
    for (int half = 0; half < 2; half++) {
        const int qt = half ? pi : (NQT - 1 - pi);

        if (half) __syncthreads();

        const size_t qbase = ((size_t)b * SEQ + (size_t)qt * 128) * DATTN + h * HD;

#pragma unroll
        for (int it = 0; it < 4; it++) {
            int idx = it * 256 + tid;
            int r = idx >> 3, c = idx & 7;
            uint32_t sw = sw128((uint32_t)(r * 128 + c * 16));
            CP_ASYNC16(sb + sw, Qh + qbase + (size_t)r * DATTN + c * 8);
        }
        auto load_stage = [&](int kt) {
            uint32_t so = sb + ST + (kt & 1) * STSZ;
            size_t kb = ((size_t)b * SEQ + (size_t)kt * 64) * DATTN + h * HD;
#pragma unroll
            for (int it = 0; it < 4; it++) {
                int idx = it * 256 + tid;
                int t = idx >> 9;
                int r = (idx >> 3) & 63;
                int c = idx & 7;
                uint32_t sw = sw128((uint32_t)(r * 128 + c * 16));
                size_t g = kb + (size_t)r * DATTN + c * 8;
                CP_ASYNC16(so + t * 8192 + sw, (t ? Vh : Kh) + g);
            }
        };
        load_stage(0);
        CP_COMMIT();

        float rs0 = 0.f, rs1 = 0.f;
        float oacc[8][4];
#pragma unroll
        for (int j = 0; j < 8; j++)
#pragma unroll
            for (int r = 0; r < 4; r++) oacc[j][r] = 0.0f;

        const int nkt = 2 * qt + 2;
        const int grow = qt * 128 + wid * 16 + gi;

        for (int kt = 0; kt < nkt; kt++) {
            CP_WAIT(0);
            __syncthreads();
            if (kt + 1 < nkt) {
                load_stage(kt + 1);
                CP_COMMIT();
            }

            const uint32_t pKH = sb + ST + (kt & 1) * STSZ;
            const uint32_t pVH = pKH + 8192;

            float sacc[8][4];
#pragma unroll
            for (int j = 0; j < 8; j++)
#pragma unroll
                for (int r = 0; r < 4; r++) sacc[j][r] = 0.0f;

#pragma unroll
            for (int ks = 0; ks < 4; ks++) {
                uint32_t qa[4];
                LDMATRIX_X4(qa[0], qa[1], qa[2], qa[3],
                            sb + sw128(a_row * 128 + ks * 32 + a_cb));
#pragma unroll
                for (int j2 = 0; j2 < 4; j2++) {
                    uint32_t boff = sw128((j2 * 16 + b_rl) * 128 + ks * 32 + b_cb);
                    uint32_t h0, h1, h2, h3;
                    LDMATRIX_X4(h0, h1, h2, h3, pKH + boff);
                    uint32_t BH0[2] = {h0, h1}, BH1[2] = {h2, h3};
                    MMA_F16(sacc[2*j2],   qa, BH0);
                    MMA_F16(sacc[2*j2+1], qa, BH1);
                }
            }

            if (kt >= 2 * qt) {
#pragma unroll
                for (int j = 0; j < 8; j++)
#pragma unroll
                    for (int r2 = 0; r2 < 2; r2++)
#pragma unroll
                        for (int e = 0; e < 2; e++) {
                            int col = kt * 64 + j * 8 + 2 * ci + e;
                            if (col > grow + r2 * 8) sacc[j][r2 * 2 + e] = -1e30f;
                        }
            }

#pragma unroll
            for (int j = 0; j < 8; j++) {
                float p0 = exp2f(sacc[j][0]);
                float p1 = exp2f(sacc[j][1]);
                float p2 = exp2f(sacc[j][2]);
                float p3 = exp2f(sacc[j][3]);
                rs0 += p0 + p1; rs1 += p2 + p3;
                sacc[j][0] = p0; sacc[j][1] = p1;
                sacc[j][2] = p2; sacc[j][3] = p3;
            }

#pragma unroll
            for (int ks = 0; ks < 4; ks++) {
                uint32_t phk[4];
                phk[0] = pack_h2(sacc[2*ks][0],   sacc[2*ks][1]);
                phk[1] = pack_h2(sacc[2*ks][2],   sacc[2*ks][3]);
                phk[2] = pack_h2(sacc[2*ks+1][0], sacc[2*ks+1][1]);
                phk[3] = pack_h2(sacc[2*ks+1][2], sacc[2*ks+1][3]);
#pragma unroll
                for (int g = 0; g < 4; g++) {
                    uint32_t voff = sw128((ks * 16 + v_key) * 128 + g * 32 + v_cb);
                    uint32_t h0, h1, h2, h3;
                    LDMATRIX_X4T(h0, h1, h2, h3, pVH + voff);
                    uint32_t VH0[2] = {h0, h1}, VH1[2] = {h2, h3};
                    MMA_F16(oacc[2*g],   phk, VH0);
                    MMA_F16(oacc[2*g+1], phk, VH1);
                }
            }
        }

        rs0 += __shfl_xor_sync(0xffffffffu, rs0, 1);
        rs0 += __shfl_xor_sync(0xffffffffu, rs0, 2);
        rs1 += __shfl_xor_sync(0xffffffffu, rs1, 1);
        rs1 += __shfl_xor_sync(0xffffffffu, rs1, 2);

        const float inv0 = 1.0f / rs0;
        const float inv1 = 1.0f / rs1;
        const size_t ob0 = ((size_t)b * SEQ + grow) * DATTN + h * HD;
        const size_t ob1 = ob0 + (size_t)8 * DATTN;
#pragma unroll
        for (int jd = 0; jd < 8; jd++) {
            int col = jd * 8 + 2 * ci;
            *(uint32_t*)(Ch + ob0 + col) =
                pack_h2(oacc[jd][0] * inv0, oacc[jd][1] * inv0);
            *(uint32_t*)(Ch + ob1 + col) =
                pack_h2(oacc[jd][2] * inv1, oacc[jd][3] * inv1);
        }
    }
}

// ---------------------------------------------------------------------------
// Launch
// ---------------------------------------------------------------------------
extern "C" void kernel_launch(void* const* d_in, const int* in_sizes, int n_in,
                              void* d_out, int out_size)
{
    const float* x  = (const float*)d_in[0];
    const float* Wq = (const float*)d_in[1];
    const float* Wk = (const float*)d_in[2];
    const float* Wv = (const float*)d_in[3];
    const float* Wo = (const float*)d_in[4];
    const float* bo = (const float*)d_in[5];
    float* out = (float*)d_out;

    __half *xh, *wqh, *wkh, *wvh, *woh, *qh, *kh, *vh, *ch;
    cudaGetSymbolAddress((void**)&xh,  g_xh);
    cudaGetSymbolAddress((void**)&wqh, g_wqh);
    cudaGetSymbolAddress((void**)&wkh, g_wkh);
    cudaGetSymbolAddress((void**)&wvh, g_wvh);
    cudaGetSymbolAddress((void**)&woh, g_woh);
    cudaGetSymbolAddress((void**)&qh,  g_qh);
    cudaGetSymbolAddress((void**)&kh,  g_kh);
    cudaGetSymbolAddress((void**)&vh,  g_vh);
    cudaGetSymbolAddress((void**)&ch,  g_ch);

    split_all<<<8192, 256>>>(x, xh, Wq, wqh, Wk, wkh, Wv, wvh, Wo, woh);

    const int smem_gemm = 98304;   // 3 stages x 32KB
    cudaFuncSetAttribute(gemm_hmma, cudaFuncAttributeMaxDynamicSharedMemorySize,
                         smem_gemm);

    // QKV fused, persistent: 768 tiles on 296 CTAs (128 thr each)
    gemm_hmma<<<296, 128, smem_gemm>>>(
        xh, wqh, wkh, wvh, nullptr, nullptr, qh, kh, vh,
        3 * NTM * NTN, /*doScaleQ=*/1);

    // Attention: qt-paired, 256 balanced CTAs, no online max
    const int smem_att = 49152;    // Q 16K + 2 stages x 16K
    cudaFuncSetAttribute(attn_hmma, cudaFuncAttributeMaxDynamicSharedMemorySize,
                         smem_att);
    attn_hmma<<<dim3(SEQ / 256, NH, BS), 256, smem_att>>>(qh, kh, vh, ch);

    // Output projection, fp32 + bias
    gemm_hmma<<<256, 128, smem_gemm>>>(
        ch, woh, nullptr, nullptr, bo, out, nullptr, nullptr, nullptr,
        NTM * NTN, /*doScaleQ=*/0);
}

// round 12
// speedup vs baseline: 1.0194x; 1.0194x over previous
#include <cuda_runtime.h>
#include <cuda_fp16.h>
#include <cstdint>
#include <math.h>

#define BS    2
#define SEQ   2048
#define DEMB  1024
#define DATTN 1024
#define NH    16
#define HD    64
#define MROWS (BS*SEQ)   // 4096

#define LOG2E 1.4426950408889634f
#define QSCALE (0.125f * LOG2E)   // folded softmax scale (log2 domain)

// ---------------------------------------------------------------------------
// Scratch (device globals -- no allocation allowed)
// ---------------------------------------------------------------------------
__device__ __half g_xh[MROWS * DEMB];
__device__ __half g_wqh[DATTN * DEMB];
__device__ __half g_wkh[DATTN * DEMB];
__device__ __half g_wvh[DATTN * DEMB];
__device__ __half g_woh[DATTN * DATTN];
__device__ __half g_qh[MROWS * DATTN];
__device__ __half g_kh[MROWS * DATTN];
__device__ __half g_vh[MROWS * DATTN];
__device__ __half g_ch[MROWS * DATTN];

// ---------------------------------------------------------------------------
// PTX helpers
// ---------------------------------------------------------------------------
__device__ __forceinline__ uint32_t smem_u32(const void* p) {
    uint32_t a;
    asm("{ .reg .u64 t; cvta.to.shared.u64 t, %1; cvt.u32.u64 %0, t; }"
        : "=r"(a) : "l"(p));
    return a;
}

#define LDMATRIX_X4(r0, r1, r2, r3, addr) \
    asm volatile("ldmatrix.sync.aligned.m8n8.x4.shared.b16 {%0,%1,%2,%3}, [%4];" \
        : "=r"(r0), "=r"(r1), "=r"(r2), "=r"(r3) : "r"(addr))

#define LDMATRIX_X4T(r0, r1, r2, r3, addr) \
    asm volatile("ldmatrix.sync.aligned.m8n8.x4.trans.shared.b16 {%0,%1,%2,%3}, [%4];" \
        : "=r"(r0), "=r"(r1), "=r"(r2), "=r"(r3) : "r"(addr))

#define MMA_F16(d, a, b) \
    asm volatile("mma.sync.aligned.m16n8k16.row.col.f32.f16.f16.f32 " \
        "{%0,%1,%2,%3}, {%4,%5,%6,%7}, {%8,%9}, {%0,%1,%2,%3};" \
        : "+f"((d)[0]), "+f"((d)[1]), "+f"((d)[2]), "+f"((d)[3]) \
        : "r"((a)[0]), "r"((a)[1]), "r"((a)[2]), "r"((a)[3]), \
          "r"((b)[0]), "r"((b)[1]))

#define CP_ASYNC16(saddr, gptr) \
    asm volatile("cp.async.cg.shared.global [%0], [%1], 16;" \
        :: "r"(saddr), "l"(gptr))
#define CP_COMMIT() asm volatile("cp.async.commit_group;" ::: "memory")
#define CP_WAIT(n)  asm volatile("cp.async.wait_group %0;" :: "n"(n) : "memory")

// packed half2 exp2 (single MUFU op for two values)
#define EX2_F16X2(out, in) \
    asm("ex2.approx.f16x2 %0, %1;" : "=r"(out) : "r"(in))

__device__ __forceinline__ uint32_t sw128(uint32_t bo) {
    return bo ^ ((bo >> 3) & 0x70);
}

__device__ __forceinline__ uint32_t pack_h2(float x, float y) {
    __half2 h = __floats2half2_rn(x, y);
    return *reinterpret_cast<uint32_t*>(&h);
}

// ---------------------------------------------------------------------------
// Fused fp32 -> fp16 convert: x + 4 weights, one launch. (unchanged)
// ---------------------------------------------------------------------------
__global__ __launch_bounds__(256) void split_all(
    const float* __restrict__ x,  __half* __restrict__ xh,
    const float* __restrict__ wq, __half* __restrict__ qh,
    const float* __restrict__ wk, __half* __restrict__ kh,
    const float* __restrict__ wv, __half* __restrict__ vh,
    const float* __restrict__ wo, __half* __restrict__ oh)
{
    int blk = blockIdx.x;
    const float* src;
    __half* hi;
    int local;
    if (blk < 4096) { src = x; hi = xh; local = blk; }
    else {
        int w = (blk - 4096) >> 10;
        local = (blk - 4096) & 1023;
        src = (w == 0) ? wq : (w == 1) ? wk : (w == 2) ? wv : wo;
        hi  = (w == 0) ? qh : (w == 1) ? kh : (w == 2) ? vh : oh;
    }
    int i = local * 1024 + threadIdx.x * 4;
    float4 v = *(const float4*)(src + i);
    *(uint2*)(hi + i) = make_uint2(pack_h2(v.x, v.y), pack_h2(v.z, v.w));
}

// ---------------------------------------------------------------------------
// Persistent HMMA fp16 GEMM (round-10 proven config): C = Ah*Bh.
// CTA 128x128, BK=64, 3x32KB stages, 256 thr / 8 warps (2x4), 2 CTAs/SM.
// ---------------------------------------------------------------------------
#define GK 1024
#define NKT (GK / 64)     // 16
#define STG 32768u
#define NTM (MROWS / 128) // 32
#define NTN (DATTN / 128) // 8

__global__ __launch_bounds__(256, 2) void gemm_hmma(
    const __half* __restrict__ Ah,
    const __half* __restrict__ Bh0, const __half* __restrict__ Bh1,
    const __half* __restrict__ Bh2,
    const float* __restrict__ bias,
    float* __restrict__ Cf,
    __half* __restrict__ H0, __half* __restrict__ H1, __half* __restrict__ H2,
    int ntiles, int doScaleQ)
{
    extern __shared__ char smem[];
    const uint32_t sbase = smem_u32(smem);

    const int tid = threadIdx.x;
    const int wid = tid >> 5;
    const int lid = tid & 31;
    const int warp_m = wid >> 2;
    const int warp_n = wid & 3;

    const uint32_t a_row = warp_m * 64 + (lid & 15);
    const uint32_t a_cb  = (lid >> 4) * 16;
    const uint32_t b_mi  = lid >> 3;
    const uint32_t b_row = warp_n * 32 + (b_mi >> 1) * 8 + (lid & 7);
    const uint32_t b_cb  = (b_mi & 1) * 16;
    const int gi = lid >> 2;
    const int ti = lid & 3;

    for (int tile = blockIdx.x; tile < ntiles; tile += gridDim.x) {
        const int z  = tile >> 8;
        const int rm = tile & 255;
        const int m0 = (rm >> 3) * 128;
        const int n0 = (rm & 7) * 128;

        const __half* Bh = (z == 0) ? Bh0 : (z == 1) ? Bh1 : Bh2;
        __half* Hs = (z == 0) ? H0 : (z == 1) ? H1 : H2;

        auto load_stage = [&](int kt, int s) {
            const uint32_t so = sbase + s * STG;
#pragma unroll
            for (int it = 0; it < 8; it++) {
                int idx = it * 256 + tid;
                int t   = idx >> 10;
                int r   = (idx >> 3) & 127;
                int c   = idx & 7;
                uint32_t sw = sw128((uint32_t)(r * 128 + c * 16));
                size_t g = (size_t)((t ? n0 : m0) + r) * GK + kt * 64 + c * 8;
                CP_ASYNC16(so + t * 16384 + sw, (t ? Bh : Ah) + g);
            }
        };

        float acc[4][4][4];
#pragma unroll
        for (int i = 0; i < 4; i++)
#pragma unroll
            for (int j = 0; j < 4; j++)
#pragma unroll
                for (int r = 0; r < 4; r++) acc[i][j][r] = 0.0f;

        load_stage(0, 0); CP_COMMIT();
        load_stage(1, 1); CP_COMMIT();

        for (int kt = 0; kt < NKT; kt++) {
            if (kt + 1 < NKT) CP_WAIT(1); else CP_WAIT(0);
            __syncthreads();
            if (kt + 2 < NKT) {
                load_stage(kt + 2, (kt + 2) % 3);
                CP_COMMIT();
            }

            const uint32_t pAH = sbase + (kt % 3) * STG;
            const uint32_t pBH = pAH + 16384;

#pragma unroll
            for (int ks = 0; ks < 4; ks++) {
                uint32_t bh[4][2];
#pragma unroll
                for (int j2 = 0; j2 < 2; j2++) {
                    uint32_t off = sw128((b_row + j2 * 16) * 128 + ks * 32 + b_cb);
                    uint32_t r0, r1, r2, r3;
                    LDMATRIX_X4(r0, r1, r2, r3, pBH + off);
                    bh[j2*2][0] = r0; bh[j2*2][1] = r1;
                    bh[j2*2+1][0] = r2; bh[j2*2+1][1] = r3;
                }
#pragma unroll
                for (int i = 0; i < 4; i++) {
                    uint32_t ah[4];
                    uint32_t off = sw128((a_row + i * 16) * 128 + ks * 32 + a_cb);
                    LDMATRIX_X4(ah[0], ah[1], ah[2], ah[3], pAH + off);
#pragma unroll
                    for (int j = 0; j < 4; j++)
                        MMA_F16(acc[i][j], ah, bh[j]);
                }
            }
        }
        __syncthreads();

        const float sc = (doScaleQ && z == 0) ? QSCALE : 1.0f;
        float* Cs = (float*)smem;
#pragma unroll
        for (int i = 0; i < 4; i++)
#pragma unroll
            for (int j = 0; j < 4; j++) {
                int row = warp_m * 64 + i * 16 + gi;
                int col = warp_n * 32 + j * 8 + ti * 2;
                Cs[row * 132 + col]           = acc[i][j][0];
                Cs[row * 132 + col + 1]       = acc[i][j][1];
                Cs[(row + 8) * 132 + col]     = acc[i][j][2];
                Cs[(row + 8) * 132 + col + 1] = acc[i][j][3];
            }
        __syncthreads();

#pragma unroll
        for (int it = 0; it < 16; it++) {
            int idx = it * 256 + tid;
            int r   = idx >> 5;
            int c4  = (idx & 31) * 4;
            float4 v = *(float4*)(Cs + r * 132 + c4);
            size_t go = (size_t)(m0 + r) * DATTN + n0 + c4;
            if (Hs) {
                *(uint2*)(Hs + go) =
                    make_uint2(pack_h2(v.x * sc, v.y * sc),
                               pack_h2(v.z * sc, v.w * sc));
            } else {
                if (bias) {
                    float4 bv = *(const float4*)(bias + n0 + c4);
                    v.x += bv.x; v.y += bv.y; v.z += bv.z; v.w += bv.w;
                }
                *(float4*)(Cf + go) = v;
            }
        }
        __syncthreads();
    }
}

// ---------------------------------------------------------------------------
// HMMA fp16 causal flash attention. Br=128, Bc=64, D=64, 2 CTAs/SM.
// NEW this round:
//  - Q fragments hoisted to registers (invariant over kt; -1/3 LDSM traffic)
//  - P = ex2.approx.f16x2 on packed S pairs (halves MUFU; pack was needed
//    anyway for the PV MMA). Mask -1e30 -> cvt saturates to -inf -> ex2 = 0.
//  - l computed by an extra ones-column MMA (lacc += P * 1): exact fp32 sum
//    of the SAME fp16 P used in PV; removes all FADD chains and shuffles.
// ---------------------------------------------------------------------------
__global__ __launch_bounds__(256, 2) void attn_hmma(
    const __half* __restrict__ Qh,
    const __half* __restrict__ Kh,
    const __half* __restrict__ Vh,
    __half* __restrict__ Ch)
{
    extern __shared__ char smem[];
    const uint32_t sb = smem_u32(smem);
    const int tid = threadIdx.x, wid = tid >> 5, lid = tid & 31;
    const int gi = lid >> 2, ci = lid & 3;
    const int pi = blockIdx.x;
    const int h = blockIdx.y, b = blockIdx.z;

    const uint32_t ST = 16384, STSZ = 16384;   // stage: KH +0, VH +8192

    const uint32_t a_row = wid * 16 + (lid & 15);
    const uint32_t a_cb  = (lid >> 4) * 16;
    const int b_mi = lid >> 3;
    const uint32_t b_rl = (uint32_t)((b_mi >> 1) * 8 + (lid & 7));
    const uint32_t b_cb = (uint32_t)((b_mi & 1) * 16);
    const uint32_t v_key = (uint32_t)(lid & 15);
    const uint32_t v_cb  = (uint32_t)((lid >> 4) * 16);

    const uint32_t ONES = 0x3C003C00u;            // half2(1, 1)
    const uint32_t ones_b[2] = {ONES, ONES};

    const int NQT = SEQ / 128;

#pragma unroll 1
    for (int half = 0; half < 2; half++) {
        const int qt = half ? pi : (NQT - 1 - pi);

        if (half) __syncthreads();   // stage+Q smem safe before reloads

        const size_t qbase = ((size_t)b * SEQ + (size_t)qt * 128) * DATTN + h * HD;

        // Q tile -> smem (group 0)
#pragma unroll
        for (int it = 0; it < 4; it++) {
            int idx = it * 256 + tid;
            int r = idx >> 3, c = idx & 7;
            uint32_t sw = sw128((uint32_t)(r * 128 + c * 16));
            CP_ASYNC16(sb + sw, Qh + qbase + (size_t)r * DATTN + c * 8);
        }
        CP_COMMIT();

        auto load_stage = [&](int kt) {
            uint32_t so = sb + ST + (kt & 1) * STSZ;
            size_t kb = ((size_t)b * SEQ + (size_t)kt * 64) * DATTN + h * HD;
#pragma unroll
            for (int it = 0; it < 4; it++) {
                int idx = it * 256 + tid;
                int t = idx >> 9;
                int r = (idx >> 3) & 63;
                int c = idx & 7;
                uint32_t sw = sw128((uint32_t)(r * 128 + c * 16));
                size_t g = kb + (size_t)r * DATTN + c * 8;
                CP_ASYNC16(so + t * 8192 + sw, (t ? Vh : Kh) + g);
            }
        };
        load_stage(0);
        CP_COMMIT();

        // Hoist Q fragments into registers (wait group-0 = Q only)
        CP_WAIT(1);
        __syncthreads();
        uint32_t qf[4][4];
#pragma unroll
        for (int ks = 0; ks < 4; ks++)
            LDMATRIX_X4(qf[ks][0], qf[ks][1], qf[ks][2], qf[ks][3],
                        sb + sw128(a_row * 128 + ks * 32 + a_cb));

        float oacc[8][4];
#pragma unroll
        for (int j = 0; j < 8; j++)
#pragma unroll
            for (int r = 0; r < 4; r++) oacc[j][r] = 0.0f;
        float lacc[4] = {0.f, 0.f, 0.f, 0.f};

        const int nkt = 2 * qt + 2;
        const int grow = qt * 128 + wid * 16 + gi;

        for (int kt = 0; kt < nkt; kt++) {
            CP_WAIT(0);
            __syncthreads();
            if (kt + 1 < nkt) {
                load_stage(kt + 1);
                CP_COMMIT();
            }

            const uint32_t pKH = sb + ST + (kt & 1) * STSZ;
            const uint32_t pVH = pKH + 8192;

            // S = Qh Kh^T
            float sacc[8][4];
#pragma unroll
            for (int j = 0; j < 8; j++)
#pragma unroll
                for (int r = 0; r < 4; r++) sacc[j][r] = 0.0f;

#pragma unroll
            for (int ks = 0; ks < 4; ks++) {
#pragma unroll
                for (int j2 = 0; j2 < 4; j2++) {
                    uint32_t boff = sw128((j2 * 16 + b_rl) * 128 + ks * 32 + b_cb);
                    uint32_t h0, h1, h2, h3;
                    LDMATRIX_X4(h0, h1, h2, h3, pKH + boff);
                    uint32_t BH0[2] = {h0, h1}, BH1[2] = {h2, h3};
                    MMA_F16(sacc[2*j2],   qf[ks], BH0);
                    MMA_F16(sacc[2*j2+1], qf[ks], BH1);
                }
            }

            // causal mask (exp2 of -inf after fp16 saturation -> 0)
            if (kt >= 2 * qt) {
#pragma unroll
                for (int j = 0; j < 8; j++)
#pragma unroll
                    for (int r2 = 0; r2 < 2; r2++)
#pragma unroll
                        for (int e = 0; e < 2; e++) {
                            int col = kt * 64 + j * 8 + 2 * ci + e;
                            if (col > grow + r2 * 8) sacc[j][r2 * 2 + e] = -1e30f;
                        }
            }

            // P = exp2(S) in f16x2; O += P*V; l += P*1 (ones-MMA)
#pragma unroll
            for (int ks = 0; ks < 4; ks++) {
                uint32_t phk[4];
                uint32_t t0 = pack_h2(sacc[2*ks][0],   sacc[2*ks][1]);
                uint32_t t1 = pack_h2(sacc[2*ks][2],   sacc[2*ks][3]);
                uint32_t t2 = pack_h2(sacc[2*ks+1][0], sacc[2*ks+1][1]);
                uint32_t t3 = pack_h2(sacc[2*ks+1][2], sacc[2*ks+1][3]);
                EX2_F16X2(phk[0], t0);
                EX2_F16X2(phk[1], t1);
                EX2_F16X2(phk[2], t2);
                EX2_F16X2(phk[3], t3);

                MMA_F16(lacc, phk, ones_b);

#pragma unroll
                for (int g = 0; g < 4; g++) {
                    uint32_t voff = sw128((ks * 16 + v_key) * 128 + g * 32 + v_cb);
                    uint32_t h0, h1, h2, h3;
                    LDMATRIX_X4T(h0, h1, h2, h3, pVH + voff);
                    uint32_t VH0[2] = {h0, h1}, VH1[2] = {h2, h3};
                    MMA_F16(oacc[2*g],   phk, VH0);
                    MMA_F16(oacc[2*g+1], phk, VH1);
                }
            }
        }

        // lacc[0] = row sum (rows gi), lacc[2] = row sum (rows gi+8)
        const float inv0 = 1.0f / lacc[0];
        const float inv1 = 1.0f / lacc[2];
        const size_t ob0 = ((size_t)b * SEQ + grow) * DATTN + h * HD;
        const size_t ob1 = ob0 + (size_t)8 * DATTN;
#pragma unroll
        for (int jd = 0; jd < 8; jd++) {
            int col = jd * 8 + 2 * ci;
            *(uint32_t*)(Ch + ob0 + col) =
                pack_h2(oacc[jd][0] * inv0, oacc[jd][1] * inv0);
            *(uint32_t*)(Ch + ob1 + col) =
                pack_h2(oacc[jd][2] * inv1, oacc[jd][3] * inv1);
        }
    }
}

// ---------------------------------------------------------------------------
// Launch
// ---------------------------------------------------------------------------
extern "C" void kernel_launch(void* const* d_in, const int* in_sizes, int n_in,
                              void* d_out, int out_size)
{
    const float* x  = (const float*)d_in[0];
    const float* Wq = (const float*)d_in[1];
    const float* Wk = (const float*)d_in[2];
    const float* Wv = (const float*)d_in[3];
    const float* Wo = (const float*)d_in[4];
    const float* bo = (const float*)d_in[5];
    float* out = (float*)d_out;

    __half *xh, *wqh, *wkh, *wvh, *woh, *qh, *kh, *vh, *ch;
    cudaGetSymbolAddress((void**)&xh,  g_xh);
    cudaGetSymbolAddress((void**)&wqh, g_wqh);
    cudaGetSymbolAddress((void**)&wkh, g_wkh);
    cudaGetSymbolAddress((void**)&wvh, g_wvh);
    cudaGetSymbolAddress((void**)&woh, g_woh);
    cudaGetSymbolAddress((void**)&qh,  g_qh);
    cudaGetSymbolAddress((void**)&kh,  g_kh);
    cudaGetSymbolAddress((void**)&vh,  g_vh);
    cudaGetSymbolAddress((void**)&ch,  g_ch);

    split_all<<<8192, 256>>>(x, xh, Wq, wqh, Wk, wkh, Wv, wvh, Wo, woh);

    const int smem_gemm = 98304;   // 3 stages x 32KB
    cudaFuncSetAttribute(gemm_hmma, cudaFuncAttributeMaxDynamicSharedMemorySize,
                         smem_gemm);

    // QKV fused, persistent: 768 tiles on 296 CTAs
    gemm_hmma<<<296, 256, smem_gemm>>>(
        xh, wqh, wkh, wvh, nullptr, nullptr, qh, kh, vh,
        3 * NTM * NTN, /*doScaleQ=*/1);

    // Attention: qt-paired balanced grid, reg-resident Q, f16x2 exp, ones-MMA l
    const int smem_att = 49152;    // Q 16K + 2 stages x 16K
    cudaFuncSetAttribute(attn_hmma, cudaFuncAttributeMaxDynamicSharedMemorySize,
                         smem_att);
    attn_hmma<<<dim3(SEQ / 256, NH, BS), 256, smem_att>>>(qh, kh, vh, ch);

    // Output projection, fp32 + bias
    gemm_hmma<<<256, 256, smem_gemm>>>(
        ch, woh, nullptr, nullptr, bo, out, nullptr, nullptr, nullptr,
        NTM * NTN, /*doScaleQ=*/0);
}

// round 13
// speedup vs baseline: 1.0340x; 1.0143x over previous
#include <cuda_runtime.h>
#include <cuda_fp16.h>
#include <cstdint>
#include <math.h>

#define BS    2
#define SEQ   2048
#define DEMB  1024
#define DATTN 1024
#define NH    16
#define HD    64
#define MROWS (BS*SEQ)   // 4096

#define LOG2E 1.4426950408889634f
#define QSCALE (0.125f * LOG2E)   // folded softmax scale (log2 domain)

// ---------------------------------------------------------------------------
// Scratch (device globals -- no allocation allowed)
// ---------------------------------------------------------------------------
__device__ __half g_xh[MROWS * DEMB];
__device__ __half g_wqh[DATTN * DEMB];
__device__ __half g_wkh[DATTN * DEMB];
__device__ __half g_wvh[DATTN * DEMB];
__device__ __half g_woh[DATTN * DATTN];
__device__ __half g_qh[MROWS * DATTN];
__device__ __half g_kh[MROWS * DATTN];
__device__ __half g_vh[MROWS * DATTN];
__device__ __half g_ch[MROWS * DATTN];

// ---------------------------------------------------------------------------
// PTX helpers
// ---------------------------------------------------------------------------
__device__ __forceinline__ uint32_t smem_u32(const void* p) {
    uint32_t a;
    asm("{ .reg .u64 t; cvta.to.shared.u64 t, %1; cvt.u32.u64 %0, t; }"
        : "=r"(a) : "l"(p));
    return a;
}

#define LDMATRIX_X4(r0, r1, r2, r3, addr) \
    asm volatile("ldmatrix.sync.aligned.m8n8.x4.shared.b16 {%0,%1,%2,%3}, [%4];" \
        : "=r"(r0), "=r"(r1), "=r"(r2), "=r"(r3) : "r"(addr))

#define LDMATRIX_X4T(r0, r1, r2, r3, addr) \
    asm volatile("ldmatrix.sync.aligned.m8n8.x4.trans.shared.b16 {%0,%1,%2,%3}, [%4];" \
        : "=r"(r0), "=r"(r1), "=r"(r2), "=r"(r3) : "r"(addr))

// fp32-accumulator MMA (projections, PV, l-sum)
#define MMA_F16(d, a, b) \
    asm volatile("mma.sync.aligned.m16n8k16.row.col.f32.f16.f16.f32 " \
        "{%0,%1,%2,%3}, {%4,%5,%6,%7}, {%8,%9}, {%0,%1,%2,%3};" \
        : "+f"((d)[0]), "+f"((d)[1]), "+f"((d)[2]), "+f"((d)[3]) \
        : "r"((a)[0]), "r"((a)[1]), "r"((a)[2]), "r"((a)[3]), \
          "r"((b)[0]), "r"((b)[1]))

// fp16-accumulator MMA (2x rate; S = QK^T only, K=64 accumulation)
#define MMA_F16ACC(d, a, b) \
    asm volatile("mma.sync.aligned.m16n8k16.row.col.f16.f16.f16.f16 " \
        "{%0,%1}, {%2,%3,%4,%5}, {%6,%7}, {%0,%1};" \
        : "+r"((d)[0]), "+r"((d)[1]) \
        : "r"((a)[0]), "r"((a)[1]), "r"((a)[2]), "r"((a)[3]), \
          "r"((b)[0]), "r"((b)[1]))

#define CP_ASYNC16(saddr, gptr) \
    asm volatile("cp.async.cg.shared.global [%0], [%1], 16;" \
        :: "r"(saddr), "l"(gptr))
#define CP_COMMIT() asm volatile("cp.async.commit_group;" ::: "memory")
#define CP_WAIT(n)  asm volatile("cp.async.wait_group %0;" :: "n"(n) : "memory")

// packed half2 exp2 (single MUFU op for two values)
#define EX2_F16X2(out, in) \
    asm("ex2.approx.f16x2 %0, %1;" : "=r"(out) : "r"(in))

__device__ __forceinline__ uint32_t sw128(uint32_t bo) {
    return bo ^ ((bo >> 3) & 0x70);
}

__device__ __forceinline__ uint32_t pack_h2(float x, float y) {
    __half2 h = __floats2half2_rn(x, y);
    return *reinterpret_cast<uint32_t*>(&h);
}

// ---------------------------------------------------------------------------
// Fused fp32 -> fp16 convert: x + 4 weights, one launch. (unchanged)
// ---------------------------------------------------------------------------
__global__ __launch_bounds__(256) void split_all(
    const float* __restrict__ x,  __half* __restrict__ xh,
    const float* __restrict__ wq, __half* __restrict__ qh,
    const float* __restrict__ wk, __half* __restrict__ kh,
    const float* __restrict__ wv, __half* __restrict__ vh,
    const float* __restrict__ wo, __half* __restrict__ oh)
{
    int blk = blockIdx.x;
    const float* src;
    __half* hi;
    int local;
    if (blk < 4096) { src = x; hi = xh; local = blk; }
    else {
        int w = (blk - 4096) >> 10;
        local = (blk - 4096) & 1023;
        src = (w == 0) ? wq : (w == 1) ? wk : (w == 2) ? wv : wo;
        hi  = (w == 0) ? qh : (w == 1) ? kh : (w == 2) ? vh : oh;
    }
    int i = local * 1024 + threadIdx.x * 4;
    float4 v = *(const float4*)(src + i);
    *(uint2*)(hi + i) = make_uint2(pack_h2(v.x, v.y), pack_h2(v.z, v.w));
}

// ---------------------------------------------------------------------------
// Persistent HMMA fp16 GEMM (unchanged): C = Ah*Bh. CTA 128x128, BK=64,
// 3x32KB stages, 256 thr / 8 warps (2x4), 2 CTAs/SM.
// ---------------------------------------------------------------------------
#define GK 1024
#define NKT (GK / 64)     // 16
#define STG 32768u
#define NTM (MROWS / 128) // 32
#define NTN (DATTN / 128) // 8

__global__ __launch_bounds__(256, 2) void gemm_hmma(
    const __half* __restrict__ Ah,
    const __half* __restrict__ Bh0, const __half* __restrict__ Bh1,
    const __half* __restrict__ Bh2,
    const float* __restrict__ bias,
    float* __restrict__ Cf,
    __half* __restrict__ H0, __half* __restrict__ H1, __half* __restrict__ H2,
    int ntiles, int doScaleQ)
{
    extern __shared__ char smem[];
    const uint32_t sbase = smem_u32(smem);

    const int tid = threadIdx.x;
    const int wid = tid >> 5;
    const int lid = tid & 31;
    const int warp_m = wid >> 2;
    const int warp_n = wid & 3;

    const uint32_t a_row = warp_m * 64 + (lid & 15);
    const uint32_t a_cb  = (lid >> 4) * 16;
    const uint32_t b_mi  = lid >> 3;
    const uint32_t b_row = warp_n * 32 + (b_mi >> 1) * 8 + (lid & 7);
    const uint32_t b_cb  = (b_mi & 1) * 16;
    const int gi = lid >> 2;
    const int ti = lid & 3;

    for (int tile = blockIdx.x; tile < ntiles; tile += gridDim.x) {
        const int z  = tile >> 8;
        const int rm = tile & 255;
        const int m0 = (rm >> 3) * 128;
        const int n0 = (rm & 7) * 128;

        const __half* Bh = (z == 0) ? Bh0 : (z == 1) ? Bh1 : Bh2;
        __half* Hs = (z == 0) ? H0 : (z == 1) ? H1 : H2;

        auto load_stage = [&](int kt, int s) {
            const uint32_t so = sbase + s * STG;
#pragma unroll
            for (int it = 0; it < 8; it++) {
                int idx = it * 256 + tid;
                int t   = idx >> 10;
                int r   = (idx >> 3) & 127;
                int c   = idx & 7;
                uint32_t sw = sw128((uint32_t)(r * 128 + c * 16));
                size_t g = (size_t)((t ? n0 : m0) + r) * GK + kt * 64 + c * 8;
                CP_ASYNC16(so + t * 16384 + sw, (t ? Bh : Ah) + g);
            }
        };

        float acc[4][4][4];
#pragma unroll
        for (int i = 0; i < 4; i++)
#pragma unroll
            for (int j = 0; j < 4; j++)
#pragma unroll
                for (int r = 0; r < 4; r++) acc[i][j][r] = 0.0f;

        load_stage(0, 0); CP_COMMIT();
        load_stage(1, 1); CP_COMMIT();

        for (int kt = 0; kt < NKT; kt++) {
            if (kt + 1 < NKT) CP_WAIT(1); else CP_WAIT(0);
            __syncthreads();
            if (kt + 2 < NKT) {
                load_stage(kt + 2, (kt + 2) % 3);
                CP_COMMIT();
            }

            const uint32_t pAH = sbase + (kt % 3) * STG;
            const uint32_t pBH = pAH + 16384;

#pragma unroll
            for (int ks = 0; ks < 4; ks++) {
                uint32_t bh[4][2];
#pragma unroll
                for (int j2 = 0; j2 < 2; j2++) {
                    uint32_t off = sw128((b_row + j2 * 16) * 128 + ks * 32 + b_cb);
                    uint32_t r0, r1, r2, r3;
                    LDMATRIX_X4(r0, r1, r2, r3, pBH + off);
                    bh[j2*2][0] = r0; bh[j2*2][1] = r1;
                    bh[j2*2+1][0] = r2; bh[j2*2+1][1] = r3;
                }
#pragma unroll
                for (int i = 0; i < 4; i++) {
                    uint32_t ah[4];
                    uint32_t off = sw128((a_row + i * 16) * 128 + ks * 32 + a_cb);
                    LDMATRIX_X4(ah[0], ah[1], ah[2], ah[3], pAH + off);
#pragma unroll
                    for (int j = 0; j < 4; j++)
                        MMA_F16(acc[i][j], ah, bh[j]);
                }
            }
        }
        __syncthreads();

        const float sc = (doScaleQ && z == 0) ? QSCALE : 1.0f;
        float* Cs = (float*)smem;
#pragma unroll
        for (int i = 0; i < 4; i++)
#pragma unroll
            for (int j = 0; j < 4; j++) {
                int row = warp_m * 64 + i * 16 + gi;
                int col = warp_n * 32 + j * 8 + ti * 2;
                Cs[row * 132 + col]           = acc[i][j][0];
                Cs[row * 132 + col + 1]       = acc[i][j][1];
                Cs[(row + 8) * 132 + col]     = acc[i][j][2];
                Cs[(row + 8) * 132 + col + 1] = acc[i][j][3];
            }
        __syncthreads();

#pragma unroll
        for (int it = 0; it < 16; it++) {
            int idx = it * 256 + tid;
            int r   = idx >> 5;
            int c4  = (idx & 31) * 4;
            float4 v = *(float4*)(Cs + r * 132 + c4);
            size_t go = (size_t)(m0 + r) * DATTN + n0 + c4;
            if (Hs) {
                *(uint2*)(Hs + go) =
                    make_uint2(pack_h2(v.x * sc, v.y * sc),
                               pack_h2(v.z * sc, v.w * sc));
            } else {
                if (bias) {
                    float4 bv = *(const float4*)(bias + n0 + c4);
                    v.x += bv.x; v.y += bv.y; v.z += bv.z; v.w += bv.w;
                }
                *(float4*)(Cf + go) = v;
            }
        }
        __syncthreads();
    }
}

// ---------------------------------------------------------------------------
// HMMA fp16 causal flash attention. Br=128, Bc=64, D=64, 2 CTAs/SM.
// NEW: S computed with fp16 accumulators (2x MMA rate; K=64 only, safe).
//      S frags are packed half2 -> ex2.approx.f16x2 applied DIRECTLY
//      (no fp32->fp16 pack at all). Mask via integer select (-inf halves).
// Kept: reg-resident Q, ones-MMA l (fp32), qt-paired balanced grid.
// ---------------------------------------------------------------------------
__global__ __launch_bounds__(256, 2) void attn_hmma(
    const __half* __restrict__ Qh,
    const __half* __restrict__ Kh,
    const __half* __restrict__ Vh,
    __half* __restrict__ Ch)
{
    extern __shared__ char smem[];
    const uint32_t sb = smem_u32(smem);
    const int tid = threadIdx.x, wid = tid >> 5, lid = tid & 31;
    const int gi = lid >> 2, ci = lid & 3;
    const int pi = blockIdx.x;
    const int h = blockIdx.y, b = blockIdx.z;

    const uint32_t ST = 16384, STSZ = 16384;   // stage: KH +0, VH +8192

    const uint32_t a_row = wid * 16 + (lid & 15);
    const uint32_t a_cb  = (lid >> 4) * 16;
    const int b_mi = lid >> 3;
    const uint32_t b_rl = (uint32_t)((b_mi >> 1) * 8 + (lid & 7));
    const uint32_t b_cb = (uint32_t)((b_mi & 1) * 16);
    const uint32_t v_key = (uint32_t)(lid & 15);
    const uint32_t v_cb  = (uint32_t)((lid >> 4) * 16);

    const uint32_t ONES = 0x3C003C00u;            // half2(1, 1)
    const uint32_t ones_b[2] = {ONES, ONES};
    const uint32_t NINF2 = 0xFC00FC00u;           // half2(-inf, -inf)

    const int NQT = SEQ / 128;

#pragma unroll 1
    for (int half = 0; half < 2; half++) {
        const int qt = half ? pi : (NQT - 1 - pi);

        if (half) __syncthreads();

        const size_t qbase = ((size_t)b * SEQ + (size_t)qt * 128) * DATTN + h * HD;

        // Q tile -> smem (group 0)
#pragma unroll
        for (int it = 0; it < 4; it++) {
            int idx = it * 256 + tid;
            int r = idx >> 3, c = idx & 7;
            uint32_t sw = sw128((uint32_t)(r * 128 + c * 16));
            CP_ASYNC16(sb + sw, Qh + qbase + (size_t)r * DATTN + c * 8);
        }
        CP_COMMIT();

        auto load_stage = [&](int kt) {
            uint32_t so = sb + ST + (kt & 1) * STSZ;
            size_t kb = ((size_t)b * SEQ + (size_t)kt * 64) * DATTN + h * HD;
#pragma unroll
            for (int it = 0; it < 4; it++) {
                int idx = it * 256 + tid;
                int t = idx >> 9;
                int r = (idx >> 3) & 63;
                int c = idx & 7;
                uint32_t sw = sw128((uint32_t)(r * 128 + c * 16));
                size_t g = kb + (size_t)r * DATTN + c * 8;
                CP_ASYNC16(so + t * 8192 + sw, (t ? Vh : Kh) + g);
            }
        };
        load_stage(0);
        CP_COMMIT();

        // Hoist Q fragments into registers
        CP_WAIT(1);
        __syncthreads();
        uint32_t qf[4][4];
#pragma unroll
        for (int ks = 0; ks < 4; ks++)
            LDMATRIX_X4(qf[ks][0], qf[ks][1], qf[ks][2], qf[ks][3],
                        sb + sw128(a_row * 128 + ks * 32 + a_cb));

        float oacc[8][4];
#pragma unroll
        for (int j = 0; j < 8; j++)
#pragma unroll
            for (int r = 0; r < 4; r++) oacc[j][r] = 0.0f;
        float lacc[4] = {0.f, 0.f, 0.f, 0.f};

        const int nkt = 2 * qt + 2;
        const int grow = qt * 128 + wid * 16 + gi;

        for (int kt = 0; kt < nkt; kt++) {
            CP_WAIT(0);
            __syncthreads();
            if (kt + 1 < nkt) {
                load_stage(kt + 1);
                CP_COMMIT();
            }

            const uint32_t pKH = sb + ST + (kt & 1) * STSZ;
            const uint32_t pVH = pKH + 8192;

            // S = Qh Kh^T -- fp16 accumulators (packed half2 pairs)
            // sacc[j][r2]: cols (2ci, 2ci+1) of n8-frag j, row gi + r2*8
            uint32_t sacc[8][2];
#pragma unroll
            for (int j = 0; j < 8; j++) { sacc[j][0] = 0u; sacc[j][1] = 0u; }

#pragma unroll
            for (int ks = 0; ks < 4; ks++) {
#pragma unroll
                for (int j2 = 0; j2 < 4; j2++) {
                    uint32_t boff = sw128((j2 * 16 + b_rl) * 128 + ks * 32 + b_cb);
                    uint32_t h0, h1, h2, h3;
                    LDMATRIX_X4(h0, h1, h2, h3, pKH + boff);
                    uint32_t BH0[2] = {h0, h1}, BH1[2] = {h2, h3};
                    MMA_F16ACC(sacc[2*j2],   qf[ks], BH0);
                    MMA_F16ACC(sacc[2*j2+1], qf[ks], BH1);
                }
            }

            // causal mask on packed halves (boundary tiles only)
            if (kt >= 2 * qt) {
#pragma unroll
                for (int j = 0; j < 8; j++)
#pragma unroll
                    for (int r2 = 0; r2 < 2; r2++) {
                        int c0  = kt * 64 + j * 8 + 2 * ci;
                        int row = grow + r2 * 8;
                        if (c0 > row)
                            sacc[j][r2] = NINF2;
                        else if (c0 + 1 > row)
                            sacc[j][r2] = (sacc[j][r2] & 0x0000FFFFu) | 0xFC000000u;
                    }
            }

            // P = exp2(S) directly on fp16 frags; O += P*V; l += P*1
#pragma unroll
            for (int ks = 0; ks < 4; ks++) {
                uint32_t phk[4];
                EX2_F16X2(phk[0], sacc[2*ks][0]);
                EX2_F16X2(phk[1], sacc[2*ks][1]);
                EX2_F16X2(phk[2], sacc[2*ks+1][0]);
                EX2_F16X2(phk[3], sacc[2*ks+1][1]);

                MMA_F16(lacc, phk, ones_b);

#pragma unroll
                for (int g = 0; g < 4; g++) {
                    uint32_t voff = sw128((ks * 16 + v_key) * 128 + g * 32 + v_cb);
                    uint32_t h0, h1, h2, h3;
                    LDMATRIX_X4T(h0, h1, h2, h3, pVH + voff);
                    uint32_t VH0[2] = {h0, h1}, VH1[2] = {h2, h3};
                    MMA_F16(oacc[2*g],   phk, VH0);
                    MMA_F16(oacc[2*g+1], phk, VH1);
                }
            }
        }

        const float inv0 = 1.0f / lacc[0];
        const float inv1 = 1.0f / lacc[2];
        const size_t ob0 = ((size_t)b * SEQ + grow) * DATTN + h * HD;
        const size_t ob1 = ob0 + (size_t)8 * DATTN;
#pragma unroll
        for (int jd = 0; jd < 8; jd++) {
            int col = jd * 8 + 2 * ci;
            *(uint32_t*)(Ch + ob0 + col) =
                pack_h2(oacc[jd][0] * inv0, oacc[jd][1] * inv0);
            *(uint32_t*)(Ch + ob1 + col) =
                pack_h2(oacc[jd][2] * inv1, oacc[jd][3] * inv1);
        }
    }
}

// ---------------------------------------------------------------------------
// Launch
// ---------------------------------------------------------------------------
extern "C" void kernel_launch(void* const* d_in, const int* in_sizes, int n_in,
                              void* d_out, int out_size)
{
    const float* x  = (const float*)d_in[0];
    const float* Wq = (const float*)d_in[1];
    const float* Wk = (const float*)d_in[2];
    const float* Wv = (const float*)d_in[3];
    const float* Wo = (const float*)d_in[4];
    const float* bo = (const float*)d_in[5];
    float* out = (float*)d_out;

    __half *xh, *wqh, *wkh, *wvh, *woh, *qh, *kh, *vh, *ch;
    cudaGetSymbolAddress((void**)&xh,  g_xh);
    cudaGetSymbolAddress((void**)&wqh, g_wqh);
    cudaGetSymbolAddress((void**)&wkh, g_wkh);
    cudaGetSymbolAddress((void**)&wvh, g_wvh);
    cudaGetSymbolAddress((void**)&woh, g_woh);
    cudaGetSymbolAddress((void**)&qh,  g_qh);
    cudaGetSymbolAddress((void**)&kh,  g_kh);
    cudaGetSymbolAddress((void**)&vh,  g_vh);
    cudaGetSymbolAddress((void**)&ch,  g_ch);

    split_all<<<8192, 256>>>(x, xh, Wq, wqh, Wk, wkh, Wv, wvh, Wo, woh);

    const int smem_gemm = 98304;   // 3 stages x 32KB
    cudaFuncSetAttribute(gemm_hmma, cudaFuncAttributeMaxDynamicSharedMemorySize,
                         smem_gemm);

    // QKV fused, persistent: 768 tiles on 296 CTAs
    gemm_hmma<<<296, 256, smem_gemm>>>(
        xh, wqh, wkh, wvh, nullptr, nullptr, qh, kh, vh,
        3 * NTM * NTN, /*doScaleQ=*/1);

    // Attention: fp16 S-accum, direct f16x2 exp, reg-resident Q, ones-MMA l
    const int smem_att = 49152;    // Q 16K + 2 stages x 16K
    cudaFuncSetAttribute(attn_hmma, cudaFuncAttributeMaxDynamicSharedMemorySize,
                         smem_att);
    attn_hmma<<<dim3(SEQ / 256, NH, BS), 256, smem_att>>>(qh, kh, vh, ch);

    // Output projection, fp32 + bias
    gemm_hmma<<<256, 256, smem_gemm>>>(
        ch, woh, nullptr, nullptr, bo, out, nullptr, nullptr, nullptr,
        NTM * NTN, /*doScaleQ=*/0);
}

// round 14
// speedup vs baseline: 1.0389x; 1.0047x over previous
#include <cuda_runtime.h>
#include <cuda_fp16.h>
#include <cstdint>
#include <math.h>

#define BS    2
#define SEQ   2048
#define DEMB  1024
#define DATTN 1024
#define NH    16
#define HD    64
#define MROWS (BS*SEQ)   // 4096

#define LOG2E 1.4426950408889634f
#define QSCALE (0.125f * LOG2E)   // folded softmax scale (log2 domain)

// ---------------------------------------------------------------------------
// Scratch (device globals -- no allocation allowed)
// ---------------------------------------------------------------------------
__device__ __half g_xh[MROWS * DEMB];
__device__ __half g_wqh[DATTN * DEMB];
__device__ __half g_wkh[DATTN * DEMB];
__device__ __half g_wvh[DATTN * DEMB];
__device__ __half g_woh[DATTN * DATTN];
__device__ __half g_qh[MROWS * DATTN];
__device__ __half g_kh[MROWS * DATTN];
__device__ __half g_vh[MROWS * DATTN];
__device__ __half g_ch[MROWS * DATTN];

// ---------------------------------------------------------------------------
// PTX helpers
// ---------------------------------------------------------------------------
__device__ __forceinline__ uint32_t smem_u32(const void* p) {
    uint32_t a;
    asm("{ .reg .u64 t; cvta.to.shared.u64 t, %1; cvt.u32.u64 %0, t; }"
        : "=r"(a) : "l"(p));
    return a;
}

#define LDMATRIX_X4(r0, r1, r2, r3, addr) \
    asm volatile("ldmatrix.sync.aligned.m8n8.x4.shared.b16 {%0,%1,%2,%3}, [%4];" \
        : "=r"(r0), "=r"(r1), "=r"(r2), "=r"(r3) : "r"(addr))

#define LDMATRIX_X4T(r0, r1, r2, r3, addr) \
    asm volatile("ldmatrix.sync.aligned.m8n8.x4.trans.shared.b16 {%0,%1,%2,%3}, [%4];" \
        : "=r"(r0), "=r"(r1), "=r"(r2), "=r"(r3) : "r"(addr))

// fp32-accumulator MMA (projections, PV, l-sum)
#define MMA_F16(d, a, b) \
    asm volatile("mma.sync.aligned.m16n8k16.row.col.f32.f16.f16.f32 " \
        "{%0,%1,%2,%3}, {%4,%5,%6,%7}, {%8,%9}, {%0,%1,%2,%3};" \
        : "+f"((d)[0]), "+f"((d)[1]), "+f"((d)[2]), "+f"((d)[3]) \
        : "r"((a)[0]), "r"((a)[1]), "r"((a)[2]), "r"((a)[3]), \
          "r"((b)[0]), "r"((b)[1]))

// fp16-accumulator MMA (2x rate; S = QK^T only, K=64 accumulation)
#define MMA_F16ACC(d, a, b) \
    asm volatile("mma.sync.aligned.m16n8k16.row.col.f16.f16.f16.f16 " \
        "{%0,%1}, {%2,%3,%4,%5}, {%6,%7}, {%0,%1};" \
        : "+r"((d)[0]), "+r"((d)[1]) \
        : "r"((a)[0]), "r"((a)[1]), "r"((a)[2]), "r"((a)[3]), \
          "r"((b)[0]), "r"((b)[1]))

#define CP_ASYNC16(saddr, gptr) \
    asm volatile("cp.async.cg.shared.global [%0], [%1], 16;" \
        :: "r"(saddr), "l"(gptr))
#define CP_COMMIT() asm volatile("cp.async.commit_group;" ::: "memory")
#define CP_WAIT(n)  asm volatile("cp.async.wait_group %0;" :: "n"(n) : "memory")

// packed half2 exp2 (single MUFU op for two values)
#define EX2_F16X2(out, in) \
    asm("ex2.approx.f16x2 %0, %1;" : "=r"(out) : "r"(in))

__device__ __forceinline__ uint32_t sw128(uint32_t bo) {
    return bo ^ ((bo >> 3) & 0x70);
}

__device__ __forceinline__ uint32_t pack_h2(float x, float y) {
    __half2 h = __floats2half2_rn(x, y);
    return *reinterpret_cast<uint32_t*>(&h);
}

// ---------------------------------------------------------------------------
// Fused fp32 -> fp16 convert: x + 4 weights, one launch. (unchanged)
// ---------------------------------------------------------------------------
__global__ __launch_bounds__(256) void split_all(
    const float* __restrict__ x,  __half* __restrict__ xh,
    const float* __restrict__ wq, __half* __restrict__ qh,
    const float* __restrict__ wk, __half* __restrict__ kh,
    const float* __restrict__ wv, __half* __restrict__ vh,
    const float* __restrict__ wo, __half* __restrict__ oh)
{
    int blk = blockIdx.x;
    const float* src;
    __half* hi;
    int local;
    if (blk < 4096) { src = x; hi = xh; local = blk; }
    else {
        int w = (blk - 4096) >> 10;
        local = (blk - 4096) & 1023;
        src = (w == 0) ? wq : (w == 1) ? wk : (w == 2) ? wv : wo;
        hi  = (w == 0) ? qh : (w == 1) ? kh : (w == 2) ? vh : oh;
    }
    int i = local * 1024 + threadIdx.x * 4;
    float4 v = *(const float4*)(src + i);
    *(uint2*)(hi + i) = make_uint2(pack_h2(v.x, v.y), pack_h2(v.z, v.w));
}

// ---------------------------------------------------------------------------
// Persistent HMMA fp16 GEMM (unchanged): C = Ah*Bh. CTA 128x128, BK=64,
// 3x32KB stages, 256 thr / 8 warps (2x4), 2 CTAs/SM.
// ---------------------------------------------------------------------------
#define GK 1024
#define NKT (GK / 64)     // 16
#define STG 32768u
#define NTM (MROWS / 128) // 32
#define NTN (DATTN / 128) // 8

__global__ __launch_bounds__(256, 2) void gemm_hmma(
    const __half* __restrict__ Ah,
    const __half* __restrict__ Bh0, const __half* __restrict__ Bh1,
    const __half* __restrict__ Bh2,
    const float* __restrict__ bias,
    float* __restrict__ Cf,
    __half* __restrict__ H0, __half* __restrict__ H1, __half* __restrict__ H2,
    int ntiles, int doScaleQ)
{
    extern __shared__ char smem[];
    const uint32_t sbase = smem_u32(smem);

    const int tid = threadIdx.x;
    const int wid = tid >> 5;
    const int lid = tid & 31;
    const int warp_m = wid >> 2;
    const int warp_n = wid & 3;

    const uint32_t a_row = warp_m * 64 + (lid & 15);
    const uint32_t a_cb  = (lid >> 4) * 16;
    const uint32_t b_mi  = lid >> 3;
    const uint32_t b_row = warp_n * 32 + (b_mi >> 1) * 8 + (lid & 7);
    const uint32_t b_cb  = (b_mi & 1) * 16;
    const int gi = lid >> 2;
    const int ti = lid & 3;

    for (int tile = blockIdx.x; tile < ntiles; tile += gridDim.x) {
        const int z  = tile >> 8;
        const int rm = tile & 255;
        const int m0 = (rm >> 3) * 128;
        const int n0 = (rm & 7) * 128;

        const __half* Bh = (z == 0) ? Bh0 : (z == 1) ? Bh1 : Bh2;
        __half* Hs = (z == 0) ? H0 : (z == 1) ? H1 : H2;

        auto load_stage = [&](int kt, int s) {
            const uint32_t so = sbase + s * STG;
#pragma unroll
            for (int it = 0; it < 8; it++) {
                int idx = it * 256 + tid;
                int t   = idx >> 10;
                int r   = (idx >> 3) & 127;
                int c   = idx & 7;
                uint32_t sw = sw128((uint32_t)(r * 128 + c * 16));
                size_t g = (size_t)((t ? n0 : m0) + r) * GK + kt * 64 + c * 8;
                CP_ASYNC16(so + t * 16384 + sw, (t ? Bh : Ah) + g);
            }
        };

        float acc[4][4][4];
#pragma unroll
        for (int i = 0; i < 4; i++)
#pragma unroll
            for (int j = 0; j < 4; j++)
#pragma unroll
                for (int r = 0; r < 4; r++) acc[i][j][r] = 0.0f;

        load_stage(0, 0); CP_COMMIT();
        load_stage(1, 1); CP_COMMIT();

        for (int kt = 0; kt < NKT; kt++) {
            if (kt + 1 < NKT) CP_WAIT(1); else CP_WAIT(0);
            __syncthreads();
            if (kt + 2 < NKT) {
                load_stage(kt + 2, (kt + 2) % 3);
                CP_COMMIT();
            }

            const uint32_t pAH = sbase + (kt % 3) * STG;
            const uint32_t pBH = pAH + 16384;

#pragma unroll
            for (int ks = 0; ks < 4; ks++) {
                uint32_t bh[4][2];
#pragma unroll
                for (int j2 = 0; j2 < 2; j2++) {
                    uint32_t off = sw128((b_row + j2 * 16) * 128 + ks * 32 + b_cb);
                    uint32_t r0, r1, r2, r3;
                    LDMATRIX_X4(r0, r1, r2, r3, pBH + off);
                    bh[j2*2][0] = r0; bh[j2*2][1] = r1;
                    bh[j2*2+1][0] = r2; bh[j2*2+1][1] = r3;
                }
#pragma unroll
                for (int i = 0; i < 4; i++) {
                    uint32_t ah[4];
                    uint32_t off = sw128((a_row + i * 16) * 128 + ks * 32 + a_cb);
                    LDMATRIX_X4(ah[0], ah[1], ah[2], ah[3], pAH + off);
#pragma unroll
                    for (int j = 0; j < 4; j++)
                        MMA_F16(acc[i][j], ah, bh[j]);
                }
            }
        }
        __syncthreads();

        const float sc = (doScaleQ && z == 0) ? QSCALE : 1.0f;
        float* Cs = (float*)smem;
#pragma unroll
        for (int i = 0; i < 4; i++)
#pragma unroll
            for (int j = 0; j < 4; j++) {
                int row = warp_m * 64 + i * 16 + gi;
                int col = warp_n * 32 + j * 8 + ti * 2;
                Cs[row * 132 + col]           = acc[i][j][0];
                Cs[row * 132 + col + 1]       = acc[i][j][1];
                Cs[(row + 8) * 132 + col]     = acc[i][j][2];
                Cs[(row + 8) * 132 + col + 1] = acc[i][j][3];
            }
        __syncthreads();

#pragma unroll
        for (int it = 0; it < 16; it++) {
            int idx = it * 256 + tid;
            int r   = idx >> 5;
            int c4  = (idx & 31) * 4;
            float4 v = *(float4*)(Cs + r * 132 + c4);
            size_t go = (size_t)(m0 + r) * DATTN + n0 + c4;
            if (Hs) {
                *(uint2*)(Hs + go) =
                    make_uint2(pack_h2(v.x * sc, v.y * sc),
                               pack_h2(v.z * sc, v.w * sc));
            } else {
                if (bias) {
                    float4 bv = *(const float4*)(bias + n0 + c4);
                    v.x += bv.x; v.y += bv.y; v.z += bv.z; v.w += bv.w;
                }
                *(float4*)(Cf + go) = v;
            }
        }
        __syncthreads();
    }
}

// ---------------------------------------------------------------------------
// HMMA fp16 causal flash attention. Br=128, Bc=64, D=64, 2 CTAs/SM.
// NEW: 3-stage K/V ring, prefetch 2 ahead, CP_WAIT(1) -> two loads in
//      flight during compute (attacks measured load-latency exposure).
// Kept: fp16 S-accum + direct f16x2 exp, reg-resident Q, ones-MMA l,
//       qt-paired balanced grid.
// ---------------------------------------------------------------------------
__global__ __launch_bounds__(256, 2) void attn_hmma(
    const __half* __restrict__ Qh,
    const __half* __restrict__ Kh,
    const __half* __restrict__ Vh,
    __half* __restrict__ Ch)
{
    extern __shared__ char smem[];
    const uint32_t sb = smem_u32(smem);
    const int tid = threadIdx.x, wid = tid >> 5, lid = tid & 31;
    const int gi = lid >> 2, ci = lid & 3;
    const int pi = blockIdx.x;
    const int h = blockIdx.y, b = blockIdx.z;

    const uint32_t ST = 16384, STSZ = 16384;   // 3 stages: KH +0, VH +8192

    const uint32_t a_row = wid * 16 + (lid & 15);
    const uint32_t a_cb  = (lid >> 4) * 16;
    const int b_mi = lid >> 3;
    const uint32_t b_rl = (uint32_t)((b_mi >> 1) * 8 + (lid & 7));
    const uint32_t b_cb = (uint32_t)((b_mi & 1) * 16);
    const uint32_t v_key = (uint32_t)(lid & 15);
    const uint32_t v_cb  = (uint32_t)((lid >> 4) * 16);

    const uint32_t ONES = 0x3C003C00u;            // half2(1, 1)
    const uint32_t ones_b[2] = {ONES, ONES};
    const uint32_t NINF2 = 0xFC00FC00u;           // half2(-inf, -inf)

    const int NQT = SEQ / 128;

#pragma unroll 1
    for (int half = 0; half < 2; half++) {
        const int qt = half ? pi : (NQT - 1 - pi);

        if (half) __syncthreads();   // all smem reads of half 0 done

        const size_t qbase = ((size_t)b * SEQ + (size_t)qt * 128) * DATTN + h * HD;

        // Q tile -> smem (own cp.async group)
#pragma unroll
        for (int it = 0; it < 4; it++) {
            int idx = it * 256 + tid;
            int r = idx >> 3, c = idx & 7;
            uint32_t sw = sw128((uint32_t)(r * 128 + c * 16));
            CP_ASYNC16(sb + sw, Qh + qbase + (size_t)r * DATTN + c * 8);
        }
        CP_COMMIT();

        auto load_stage = [&](int kt) {
            uint32_t so = sb + ST + (uint32_t)(kt % 3) * STSZ;
            size_t kb = ((size_t)b * SEQ + (size_t)kt * 64) * DATTN + h * HD;
#pragma unroll
            for (int it = 0; it < 4; it++) {
                int idx = it * 256 + tid;
                int t = idx >> 9;
                int r = (idx >> 3) & 63;
                int c = idx & 7;
                uint32_t sw = sw128((uint32_t)(r * 128 + c * 16));
                size_t g = kb + (size_t)r * DATTN + c * 8;
                CP_ASYNC16(so + t * 8192 + sw, (t ? Vh : Kh) + g);
            }
        };
        load_stage(0); CP_COMMIT();
        load_stage(1); CP_COMMIT();   // nkt >= 2 always

        // Hoist Q fragments (wait leaves <=2 pending = the two K/V stages)
        CP_WAIT(2);
        __syncthreads();
        uint32_t qf[4][4];
#pragma unroll
        for (int ks = 0; ks < 4; ks++)
            LDMATRIX_X4(qf[ks][0], qf[ks][1], qf[ks][2], qf[ks][3],
                        sb + sw128(a_row * 128 + ks * 32 + a_cb));

        float oacc[8][4];
#pragma unroll
        for (int j = 0; j < 8; j++)
#pragma unroll
            for (int r = 0; r < 4; r++) oacc[j][r] = 0.0f;
        float lacc[4] = {0.f, 0.f, 0.f, 0.f};

        const int nkt = 2 * qt + 2;
        const int grow = qt * 128 + wid * 16 + gi;

        for (int kt = 0; kt < nkt; kt++) {
            if (kt + 1 < nkt) CP_WAIT(1); else CP_WAIT(0);
            __syncthreads();
            if (kt + 2 < nkt) {
                load_stage(kt + 2);
                CP_COMMIT();
            }

            const uint32_t pKH = sb + ST + (uint32_t)(kt % 3) * STSZ;
            const uint32_t pVH = pKH + 8192;

            // S = Qh Kh^T -- fp16 accumulators (packed half2 pairs)
            uint32_t sacc[8][2];
#pragma unroll
            for (int j = 0; j < 8; j++) { sacc[j][0] = 0u; sacc[j][1] = 0u; }

#pragma unroll
            for (int ks = 0; ks < 4; ks++) {
#pragma unroll
                for (int j2 = 0; j2 < 4; j2++) {
                    uint32_t boff = sw128((j2 * 16 + b_rl) * 128 + ks * 32 + b_cb);
                    uint32_t h0, h1, h2, h3;
                    LDMATRIX_X4(h0, h1, h2, h3, pKH + boff);
                    uint32_t BH0[2] = {h0, h1}, BH1[2] = {h2, h3};
                    MMA_F16ACC(sacc[2*j2],   qf[ks], BH0);
                    MMA_F16ACC(sacc[2*j2+1], qf[ks], BH1);
                }
            }

            // causal mask on packed halves (boundary tiles only)
            if (kt >= 2 * qt) {
#pragma unroll
                for (int j = 0; j < 8; j++)
#pragma unroll
                    for (int r2 = 0; r2 < 2; r2++) {
                        int c0  = kt * 64 + j * 8 + 2 * ci;
                        int row = grow + r2 * 8;
                        if (c0 > row)
                            sacc[j][r2] = NINF2;
                        else if (c0 + 1 > row)
                            sacc[j][r2] = (sacc[j][r2] & 0x0000FFFFu) | 0xFC000000u;
                    }
            }

            // P = exp2(S) directly on fp16 frags; O += P*V; l += P*1
#pragma unroll
            for (int ks = 0; ks < 4; ks++) {
                uint32_t phk[4];
                EX2_F16X2(phk[0], sacc[2*ks][0]);
                EX2_F16X2(phk[1], sacc[2*ks][1]);
                EX2_F16X2(phk[2], sacc[2*ks+1][0]);
                EX2_F16X2(phk[3], sacc[2*ks+1][1]);

                MMA_F16(lacc, phk, ones_b);

#pragma unroll
                for (int g = 0; g < 4; g++) {
                    uint32_t voff = sw128((ks * 16 + v_key) * 128 + g * 32 + v_cb);
                    uint32_t h0, h1, h2, h3;
                    LDMATRIX_X4T(h0, h1, h2, h3, pVH + voff);
                    uint32_t VH0[2] = {h0, h1}, VH1[2] = {h2, h3};
                    MMA_F16(oacc[2*g],   phk, VH0);
                    MMA_F16(oacc[2*g+1], phk, VH1);
                }
            }
        }

        const float inv0 = 1.0f / lacc[0];
        const float inv1 = 1.0f / lacc[2];
        const size_t ob0 = ((size_t)b * SEQ + grow) * DATTN + h * HD;
        const size_t ob1 = ob0 + (size_t)8 * DATTN;
#pragma unroll
        for (int jd = 0; jd < 8; jd++) {
            int col = jd * 8 + 2 * ci;
            *(uint32_t*)(Ch + ob0 + col) =
                pack_h2(oacc[jd][0] * inv0, oacc[jd][1] * inv0);
            *(uint32_t*)(Ch + ob1 + col) =
                pack_h2(oacc[jd][2] * inv1, oacc[jd][3] * inv1);
        }
    }
}

// ---------------------------------------------------------------------------
// Launch
// ---------------------------------------------------------------------------
extern "C" void kernel_launch(void* const* d_in, const int* in_sizes, int n_in,
                              void* d_out, int out_size)
{
    const float* x  = (const float*)d_in[0];
    const float* Wq = (const float*)d_in[1];
    const float* Wk = (const float*)d_in[2];
    const float* Wv = (const float*)d_in[3];
    const float* Wo = (const float*)d_in[4];
    const float* bo = (const float*)d_in[5];
    float* out = (float*)d_out;

    __half *xh, *wqh, *wkh, *wvh, *woh, *qh, *kh, *vh, *ch;
    cudaGetSymbolAddress((void**)&xh,  g_xh);
    cudaGetSymbolAddress((void**)&wqh, g_wqh);
    cudaGetSymbolAddress((void**)&wkh, g_wkh);
    cudaGetSymbolAddress((void**)&wvh, g_wvh);
    cudaGetSymbolAddress((void**)&woh, g_woh);
    cudaGetSymbolAddress((void**)&qh,  g_qh);
    cudaGetSymbolAddress((void**)&kh,  g_kh);
    cudaGetSymbolAddress((void**)&vh,  g_vh);
    cudaGetSymbolAddress((void**)&ch,  g_ch);

    split_all<<<8192, 256>>>(x, xh, Wq, wqh, Wk, wkh, Wv, wvh, Wo, woh);

    const int smem_gemm = 98304;   // 3 stages x 32KB
    cudaFuncSetAttribute(gemm_hmma, cudaFuncAttributeMaxDynamicSharedMemorySize,
                         smem_gemm);

    // QKV fused, persistent: 768 tiles on 296 CTAs
    gemm_hmma<<<296, 256, smem_gemm>>>(
        xh, wqh, wkh, wvh, nullptr, nullptr, qh, kh, vh,
        3 * NTM * NTN, /*doScaleQ=*/1);

    // Attention: 3-stage K/V ring, 2-deep prefetch
    const int smem_att = 65536;    // Q 16K + 3 stages x 16K
    cudaFuncSetAttribute(attn_hmma, cudaFuncAttributeMaxDynamicSharedMemorySize,
                         smem_att);
    attn_hmma<<<dim3(SEQ / 256, NH, BS), 256, smem_att>>>(qh, kh, vh, ch);

    // Output projection, fp32 + bias
    gemm_hmma<<<256, 256, smem_gemm>>>(
        ch, woh, nullptr, nullptr, bo, out, nullptr, nullptr, nullptr,
        NTM * NTN, /*doScaleQ=*/0);
}